// round 11
// baseline (speedup 1.0000x reference)
#include <cuda_runtime.h>
#include <stdint.h>

// TopK_31877247271346: per-row top-64 of x[4096][16384] fp32 scattered into zeros.
// Split into pure-direction streams (pure write measured 6.4 TB/s vs 5.2 mixed):
//   K1 zero_kernel: zero-fill out (pure 256 MB write stream)
//   K2 topk_select_kernel: pure 256 MB read + select + <=64 scatter per row
// K2 (lean, from R8): SIMD candidate mask (x >= 2.25 via signed hi-16 compare,
// ~200 cands/row), warp-aggregated compaction into SMEM, one barrier, warps
// 1..15 exit, warp 0 privately radix-selects + tie-breaks + scatters.
// Exact key-space fallback via global re-reads if count outside [K, CAP].

#define NROWS 4096
#define NCOLS 16384
#define KSEL  64
#define NT    512
#define VPT   8
#define CAP   512

// zero kernel config (measured ~6.4 TB/s in R6)
#define ZNT   256
#define ZVPT  8
#define ZTOT  (NROWS * (size_t)NCOLS / 4)              // uint4 count
#define ZGRID (int)(ZTOT / (ZNT * ZVPT))               // 8192

__device__ __forceinline__ uint32_t f2key(uint32_t a) {
    return (a & 0x80000000u) ? ~a : (a | 0x80000000u);
}
__device__ __forceinline__ float key2f(uint32_t u) {
    return __uint_as_float((u & 0x80000000u) ? (u ^ 0x80000000u) : ~u);
}

__global__ void __launch_bounds__(ZNT)
zero_kernel(uint4* __restrict__ out)
{
    const size_t base = (size_t)blockIdx.x * (ZNT * ZVPT) + threadIdx.x;
    const uint4 z = make_uint4(0u, 0u, 0u, 0u);
    #pragma unroll
    for (int i = 0; i < ZVPT; i++) out[base + (size_t)i * ZNT] = z;
}

__global__ void __launch_bounds__(NT, 4)
topk_select_kernel(const float* __restrict__ x, float* __restrict__ out)
{
    __shared__ uint32_t hist[256];
    __shared__ uint32_t slot[32];     // fallback per-iteration counters
    __shared__ uint32_t nCandS;
    __shared__ uint32_t skey[CAP];
    __shared__ uint16_t scol[CAP];

    const int tid  = threadIdx.x;
    const int lane = tid & 31;
    const int wid  = tid >> 5;
    const size_t rowOff = (size_t)blockIdx.x * NCOLS;
    const uint4* __restrict__ xrow4 = reinterpret_cast<const uint4*>(x + rowOff);

    // ---- batch-0 loads in flight while smem is initialized ----
    uint4 v[4];
    #pragma unroll
    for (int i = 0; i < 4; i++) v[i] = xrow4[tid + i * NT];

    if (tid < 256) hist[tid] = 0;
    if (tid < 32)  slot[tid] = 0;
    if (tid == 0)  nCandS = 0;
    __syncthreads();

    // ---- SIMD candidate mask: bit (4g+c) set iff element >= 2.25f ----
    // hi-16 signed compare vs 0x4010 (2.25f); negatives excluded by sign.
    uint32_t m = 0;
    #pragma unroll
    for (int i = 0; i < 4; i++) {
        uint32_t p0 = __byte_perm(v[i].x, v[i].y, 0x7632);  // [y_hi16 : x_hi16]
        uint32_t p1 = __byte_perm(v[i].z, v[i].w, 0x7632);  // [w_hi16 : z_hi16]
        uint32_t r0 = __vsetges2(p0, 0x40104010u);
        uint32_t r1 = __vsetges2(p1, 0x40104010u);
        uint32_t nib = __dp4a(r1, 0x00080004u, __dp4a(r0, 0x00020001u, 0u));
        m |= nib << (4 * i);
    }
    #pragma unroll
    for (int i = 0; i < 4; i++) v[i] = xrow4[tid + (4 + i) * NT];   // batch 1
    #pragma unroll
    for (int i = 0; i < 4; i++) {
        uint32_t p0 = __byte_perm(v[i].x, v[i].y, 0x7632);
        uint32_t p1 = __byte_perm(v[i].z, v[i].w, 0x7632);
        uint32_t r0 = __vsetges2(p0, 0x40104010u);
        uint32_t r1 = __vsetges2(p1, 0x40104010u);
        uint32_t nib = __dp4a(r1, 0x00080004u, __dp4a(r0, 0x00020001u, 0u));
        m |= nib << (16 + 4 * i);
    }

    // ---- warp-aggregated compaction (1 atomic/warp), sparse extraction ----
    {
        const uint32_t c = (uint32_t)__popc(m);
        uint32_t pre = c;
        #pragma unroll
        for (int off = 1; off < 32; off <<= 1) {
            uint32_t t = __shfl_up_sync(0xFFFFFFFFu, pre, off);
            if (lane >= off) pre += t;
        }
        uint32_t wbase = 0;
        if (lane == 31 && pre) wbase = atomicAdd(&nCandS, pre);
        wbase = __shfl_sync(0xFFFFFFFFu, wbase, 31);
        uint32_t base = wbase + (pre - c);

        uint32_t mm = m;
        while (mm) {                       // ~0.4 iterations/thread on average
            const int e = __ffs(mm) - 1; mm &= mm - 1;
            const int g = e >> 2, cc = e & 3;
            const uint32_t col = (uint32_t)(tid + g * NT) * 4u + (uint32_t)cc;
            if (base < CAP) {
                skey[base] = __float_as_uint(__ldg(x + rowOff + col));  // L2 hit
                scol[base] = (uint16_t)col;
            }
            base++;
        }
    }
    __syncthreads();
    const uint32_t nc = nCandS;

    if (nc >= KSEL && nc <= CAP) {
        if (wid != 0) return;             // warps 1..15 done: free issue slots

        // ======== warp-0 private select (no block barriers) ========
        uint32_t prefix = 0, remK = KSEL, cntEq = 0;
        #pragma unroll 1
        for (int shift = 24; shift >= 0; shift -= 8) {
            const uint32_t pmask = (shift == 24) ? 0u : (0xFFFFFFFFu << (shift + 8));
            for (int j = lane; j < (int)nc; j += 32) {
                const uint32_t u = skey[j];
                if ((u & pmask) == prefix)
                    atomicAdd(&hist[(u >> shift) & 255u], 1u);
            }
            __syncwarp();

            // suffix scan over 256 buckets (lane owns 8), pick, re-zero
            uint32_t local[8], sum = 0;
            #pragma unroll
            for (int j = 0; j < 8; j++) { local[j] = hist[lane*8 + j]; sum += local[j]; }
            #pragma unroll
            for (int j = 0; j < 8; j++) hist[lane*8 + j] = 0;

            uint32_t tot = sum;
            #pragma unroll
            for (int off = 1; off < 32; off <<= 1) {
                uint32_t t = __shfl_down_sync(0xFFFFFFFFu, tot, off);
                if (lane + off < 32) tot += t;
            }
            uint32_t run = tot - sum;
            uint32_t myP = 0, myR = 0, myE = 0;
            bool found = false;
            #pragma unroll
            for (int j = 7; j >= 0; j--) {
                const uint32_t inc = run + local[j];
                if (inc >= remK && run < remK) {      // exactly one (lane,j)
                    found = true;
                    myP = prefix | ((uint32_t)(lane*8 + j) << shift);
                    myR = remK - run;
                    myE = local[j];
                }
                run = inc;
            }
            const uint32_t bal = __ballot_sync(0xFFFFFFFFu, found);
            const int src = __ffs(bal) - 1;
            prefix = __shfl_sync(0xFFFFFFFFu, myP, src);
            remK   = __shfl_sync(0xFFFFFFFFu, myR, src);
            cntEq  = __shfl_sync(0xFFFFFFFFu, myE, src);
            __syncwarp();
        }
        const uint32_t T = prefix;

        // ---- stable lowest-index tie-break (rare), warp-local ----
        uint32_t tieCut = 0xFFFFFFFFu;
        if (cntEq != remK) {
            int lo = 0, hi = NCOLS - 1;
            while (lo < hi) {                 // <=14 iterations
                const int mid = (lo + hi) >> 1;
                uint32_t c = 0;
                for (int j = lane; j < (int)nc; j += 32)
                    c += (skey[j] == T && (int)scol[j] <= mid) ? 1u : 0u;
                c = __reduce_add_sync(0xFFFFFFFFu, c);
                if (c >= remK) hi = mid; else lo = mid + 1;
            }
            tieCut = (uint32_t)lo;
        }

        // ---- scatter winners over zeros (zeroed by the prior kernel) ----
        for (int j = lane; j < (int)nc; j += 32) {
            const uint32_t u = skey[j];
            const uint32_t col = scol[j];
            if (u > T || (u == T && col <= tieCut))
                out[rowOff + col] = __uint_as_float(u);
        }
        return;
    }

    // ================= FALLBACK (exact, key-space, via global re-reads) ======
    // out is already zero from zero_kernel; only winners are written.
    {
        const float4* __restrict__ xrow = reinterpret_cast<const float4*>(x + rowOff);
        __syncthreads();
        if (tid < 32) slot[tid] = 0;
        __syncthreads();

        unsigned long long blo = 0ull, bhi = 0x100000000ull;
        int it = 0;
        while (bhi - blo > 1ull) {
            const uint32_t mid = (uint32_t)((blo + bhi) >> 1);
            uint32_t c = 0;
            for (int i = 0; i < VPT; i++) {
                float4 vv = xrow[tid + i * NT];
                c += (f2key(__float_as_uint(vv.x)) >= mid);
                c += (f2key(__float_as_uint(vv.y)) >= mid);
                c += (f2key(__float_as_uint(vv.z)) >= mid);
                c += (f2key(__float_as_uint(vv.w)) >= mid);
            }
            #pragma unroll
            for (int off = 16; off >= 1; off >>= 1)
                c += __shfl_down_sync(0xFFFFFFFFu, c, off);
            if (lane == 0 && c) atomicAdd(&slot[it & 31], c);
            __syncthreads();
            if (slot[it & 31] >= KSEL) blo = (unsigned long long)mid;
            else                       bhi = (unsigned long long)mid;
            it++;
            if ((it & 31) == 0) {
                __syncthreads();
                if (tid < 32) slot[tid] = 0;
                __syncthreads();
            }
        }
        const uint32_t T = (uint32_t)blo;

        __syncthreads();
        if (tid < 32) slot[tid] = 0;
        __syncthreads();
        {
            uint32_t ca = 0, ce = 0;
            for (int i = 0; i < VPT; i++) {
                float4 vv = xrow[tid + i * NT];
                const uint32_t k0 = f2key(__float_as_uint(vv.x));
                const uint32_t k1 = f2key(__float_as_uint(vv.y));
                const uint32_t k2 = f2key(__float_as_uint(vv.z));
                const uint32_t k3 = f2key(__float_as_uint(vv.w));
                ca += (k0 > T) + (k1 > T) + (k2 > T) + (k3 > T);
                ce += (k0 == T) + (k1 == T) + (k2 == T) + (k3 == T);
            }
            #pragma unroll
            for (int off = 16; off >= 1; off >>= 1) {
                ca += __shfl_down_sync(0xFFFFFFFFu, ca, off);
                ce += __shfl_down_sync(0xFFFFFFFFu, ce, off);
            }
            if (lane == 0) { atomicAdd(&slot[0], ca); atomicAdd(&slot[1], ce); }
        }
        __syncthreads();
        const uint32_t abv  = slot[0];
        const uint32_t eq   = slot[1];
        const uint32_t remK = KSEL - abv;

        uint32_t tieCut = 0xFFFFFFFFu;
        if (eq != remK) {
            __syncthreads();
            if (tid < 32) slot[tid] = 0;
            __syncthreads();
            int lo = 0, hi = NCOLS - 1, ti = 0;
            while (lo < hi) {
                const int mid = (lo + hi) >> 1;
                uint32_t c = 0;
                for (int i = 0; i < VPT; i++) {
                    float4 vv = xrow[tid + i * NT];
                    const int col0 = (tid + i * NT) * 4;
                    c += (f2key(__float_as_uint(vv.x)) == T && col0 + 0 <= mid);
                    c += (f2key(__float_as_uint(vv.y)) == T && col0 + 1 <= mid);
                    c += (f2key(__float_as_uint(vv.z)) == T && col0 + 2 <= mid);
                    c += (f2key(__float_as_uint(vv.w)) == T && col0 + 3 <= mid);
                }
                #pragma unroll
                for (int off = 16; off >= 1; off >>= 1)
                    c += __shfl_down_sync(0xFFFFFFFFu, c, off);
                if (lane == 0 && c) atomicAdd(&slot[ti & 31], c);
                __syncthreads();
                if (slot[ti & 31] >= remK) hi = mid; else lo = mid + 1;
                ti++;
                if ((ti & 31) == 0) {
                    __syncthreads();
                    if (tid < 32) slot[tid] = 0;
                    __syncthreads();
                }
            }
            tieCut = (uint32_t)lo;
        }

        for (int i = 0; i < VPT; i++) {
            float4 vv = xrow[tid + i * NT];
            const uint32_t col0 = (uint32_t)(tid + i * NT) * 4u;
            const uint32_t k0 = f2key(__float_as_uint(vv.x));
            const uint32_t k1 = f2key(__float_as_uint(vv.y));
            const uint32_t k2 = f2key(__float_as_uint(vv.z));
            const uint32_t k3 = f2key(__float_as_uint(vv.w));
            if (k0 > T || (k0 == T && col0 + 0u <= tieCut)) out[rowOff + col0 + 0] = key2f(k0);
            if (k1 > T || (k1 == T && col0 + 1u <= tieCut)) out[rowOff + col0 + 1] = key2f(k1);
            if (k2 > T || (k2 == T && col0 + 2u <= tieCut)) out[rowOff + col0 + 2] = key2f(k2);
            if (k3 > T || (k3 == T && col0 + 3u <= tieCut)) out[rowOff + col0 + 3] = key2f(k3);
        }
    }
}

extern "C" void kernel_launch(void* const* d_in, const int* in_sizes, int n_in,
                              void* d_out, int out_size)
{
    const float* x = (const float*)d_in[0];
    float* out = (float*)d_out;
    (void)in_sizes; (void)n_in; (void)out_size;

    zero_kernel<<<ZGRID, ZNT>>>(reinterpret_cast<uint4*>(out));
    topk_select_kernel<<<NROWS, NT>>>(x, out);
}

// round 12
// speedup vs baseline: 1.1928x; 1.1928x over previous
#include <cuda_runtime.h>
#include <stdint.h>

// TopK_31877247271346: per-row top-64 of x[4096][16384] fp32 scattered into zeros.
// Fused single kernel (split variants measured slower: streams must overlap).
// One CTA (512 threads) per row:
//  - batch-0 loads issued, then full-row zero stores IMMEDIATELY (no barrier)
//  - SIMD candidate mask (x >= 2.25 via signed hi-16 compare, ~200 cands/row)
//  - one barrier; warp-aggregated compaction into SMEM
//  - one barrier; warps 1..15 exit; warp 0 privately zeroes hist, runs the
//    exact 4-round radix select, stable tie-break, and <=64-element scatter
// Exact key-space fallback via global re-reads if count outside [K, CAP].

#define NROWS 4096
#define NCOLS 16384
#define KSEL  64
#define NT    512
#define VPT   8
#define CAP   512

__device__ __forceinline__ uint32_t f2key(uint32_t a) {
    return (a & 0x80000000u) ? ~a : (a | 0x80000000u);
}
__device__ __forceinline__ float key2f(uint32_t u) {
    return __uint_as_float((u & 0x80000000u) ? (u ^ 0x80000000u) : ~u);
}

__global__ void __launch_bounds__(NT, 4)
topk_scatter_kernel(const float* __restrict__ x, float* __restrict__ out)
{
    __shared__ uint32_t hist[256];
    __shared__ uint32_t slot[32];     // fallback-only counters
    __shared__ uint32_t nCandS;
    __shared__ uint32_t skey[CAP];
    __shared__ uint16_t scol[CAP];

    const int tid  = threadIdx.x;
    const int lane = tid & 31;
    const int wid  = tid >> 5;
    const size_t rowOff = (size_t)blockIdx.x * NCOLS;
    const uint4* __restrict__ xrow4 = reinterpret_cast<const uint4*>(x + rowOff);
    uint4* __restrict__ orow = reinterpret_cast<uint4*>(out + rowOff);

    // ---- batch-0 loads in flight ----
    uint4 v[4];
    #pragma unroll
    for (int i = 0; i < 4; i++) v[i] = xrow4[tid + i * NT];

    // ---- full-row zero stores immediately: both HBM directions live at once ----
    const uint4 z4 = make_uint4(0u, 0u, 0u, 0u);
    #pragma unroll
    for (int i = 0; i < VPT; i++) __stcs(&orow[tid + i * NT], z4);

    if (tid == 0) nCandS = 0;

    // ---- SIMD candidate mask: bit (4g+c) set iff element >= 2.25f ----
    // hi-16 signed compare vs 0x4010 (2.25f); negatives excluded by sign bit.
    uint32_t m = 0;
    #pragma unroll
    for (int i = 0; i < 4; i++) {
        uint32_t p0 = __byte_perm(v[i].x, v[i].y, 0x7632);  // [y_hi16 : x_hi16]
        uint32_t p1 = __byte_perm(v[i].z, v[i].w, 0x7632);  // [w_hi16 : z_hi16]
        uint32_t r0 = __vsetges2(p0, 0x40104010u);
        uint32_t r1 = __vsetges2(p1, 0x40104010u);
        uint32_t nib = __dp4a(r1, 0x00080004u, __dp4a(r0, 0x00020001u, 0u));
        m |= nib << (4 * i);
    }
    #pragma unroll
    for (int i = 0; i < 4; i++) v[i] = xrow4[tid + (4 + i) * NT];   // batch 1
    #pragma unroll
    for (int i = 0; i < 4; i++) {
        uint32_t p0 = __byte_perm(v[i].x, v[i].y, 0x7632);
        uint32_t p1 = __byte_perm(v[i].z, v[i].w, 0x7632);
        uint32_t r0 = __vsetges2(p0, 0x40104010u);
        uint32_t r1 = __vsetges2(p1, 0x40104010u);
        uint32_t nib = __dp4a(r1, 0x00080004u, __dp4a(r0, 0x00020001u, 0u));
        m |= nib << (16 + 4 * i);
    }
    __syncthreads();   // nCandS=0 visible before compaction atomics

    // ---- warp-aggregated compaction (1 atomic/warp), sparse extraction ----
    {
        const uint32_t c = (uint32_t)__popc(m);
        uint32_t pre = c;
        #pragma unroll
        for (int off = 1; off < 32; off <<= 1) {
            uint32_t t = __shfl_up_sync(0xFFFFFFFFu, pre, off);
            if (lane >= off) pre += t;
        }
        uint32_t wbase = 0;
        if (lane == 31 && pre) wbase = atomicAdd(&nCandS, pre);
        wbase = __shfl_sync(0xFFFFFFFFu, wbase, 31);
        uint32_t base = wbase + (pre - c);

        uint32_t mm = m;
        while (mm) {                       // ~0.4 iterations/thread on average
            const int e = __ffs(mm) - 1; mm &= mm - 1;
            const int g = e >> 2, cc = e & 3;
            const uint32_t col = (uint32_t)(tid + g * NT) * 4u + (uint32_t)cc;
            if (base < CAP) {
                skey[base] = __float_as_uint(__ldg(x + rowOff + col));  // L2 hit
                scol[base] = (uint16_t)col;
            }
            base++;
        }
    }
    __syncthreads();
    const uint32_t nc = nCandS;

    if (nc >= KSEL && nc <= CAP) {
        if (wid != 0) return;             // warps 1..15 done: free issue slots

        // ======== warp-0 private select (no block barriers) ========
        #pragma unroll
        for (int j = 0; j < 8; j++) hist[lane * 8 + j] = 0;   // private init
        __syncwarp();

        uint32_t prefix = 0, remK = KSEL, cntEq = 0;
        #pragma unroll 1
        for (int shift = 24; shift >= 0; shift -= 8) {
            const uint32_t pmask = (shift == 24) ? 0u : (0xFFFFFFFFu << (shift + 8));
            for (int j = lane; j < (int)nc; j += 32) {
                const uint32_t u = skey[j];
                if ((u & pmask) == prefix)
                    atomicAdd(&hist[(u >> shift) & 255u], 1u);
            }
            __syncwarp();

            // suffix scan over 256 buckets (lane owns 8), pick, re-zero
            uint32_t local[8], sum = 0;
            #pragma unroll
            for (int j = 0; j < 8; j++) { local[j] = hist[lane*8 + j]; sum += local[j]; }
            #pragma unroll
            for (int j = 0; j < 8; j++) hist[lane*8 + j] = 0;

            uint32_t tot = sum;
            #pragma unroll
            for (int off = 1; off < 32; off <<= 1) {
                uint32_t t = __shfl_down_sync(0xFFFFFFFFu, tot, off);
                if (lane + off < 32) tot += t;
            }
            uint32_t run = tot - sum;
            uint32_t myP = 0, myR = 0, myE = 0;
            bool found = false;
            #pragma unroll
            for (int j = 7; j >= 0; j--) {
                const uint32_t inc = run + local[j];
                if (inc >= remK && run < remK) {      // exactly one (lane,j)
                    found = true;
                    myP = prefix | ((uint32_t)(lane*8 + j) << shift);
                    myR = remK - run;
                    myE = local[j];
                }
                run = inc;
            }
            const uint32_t bal = __ballot_sync(0xFFFFFFFFu, found);
            const int src = __ffs(bal) - 1;
            prefix = __shfl_sync(0xFFFFFFFFu, myP, src);
            remK   = __shfl_sync(0xFFFFFFFFu, myR, src);
            cntEq  = __shfl_sync(0xFFFFFFFFu, myE, src);
            __syncwarp();
        }
        const uint32_t T = prefix;

        // ---- stable lowest-index tie-break (rare), warp-local ----
        uint32_t tieCut = 0xFFFFFFFFu;
        if (cntEq != remK) {
            int lo = 0, hi = NCOLS - 1;
            while (lo < hi) {                 // <=14 iterations
                const int mid = (lo + hi) >> 1;
                uint32_t c = 0;
                for (int j = lane; j < (int)nc; j += 32)
                    c += (skey[j] == T && (int)scol[j] <= mid) ? 1u : 0u;
                c = __reduce_add_sync(0xFFFFFFFFu, c);
                if (c >= remK) hi = mid; else lo = mid + 1;
            }
            tieCut = (uint32_t)lo;
        }

        // ---- scatter winners over the zeros (same-CTA barrier ordering) ----
        for (int j = lane; j < (int)nc; j += 32) {
            const uint32_t u = skey[j];
            const uint32_t col = scol[j];
            if (u > T || (u == T && col <= tieCut))
                __stcs(&out[rowOff + col], __uint_as_float(u));
        }
        return;
    }

    // ================= FALLBACK (exact, key-space, via global re-reads) ======
    {
        const float4* __restrict__ xrow = reinterpret_cast<const float4*>(x + rowOff);
        __syncthreads();
        if (tid < 32) slot[tid] = 0;
        __syncthreads();

        unsigned long long blo = 0ull, bhi = 0x100000000ull;
        int it = 0;
        while (bhi - blo > 1ull) {
            const uint32_t mid = (uint32_t)((blo + bhi) >> 1);
            uint32_t c = 0;
            for (int i = 0; i < VPT; i++) {
                float4 vv = xrow[tid + i * NT];
                c += (f2key(__float_as_uint(vv.x)) >= mid);
                c += (f2key(__float_as_uint(vv.y)) >= mid);
                c += (f2key(__float_as_uint(vv.z)) >= mid);
                c += (f2key(__float_as_uint(vv.w)) >= mid);
            }
            #pragma unroll
            for (int off = 16; off >= 1; off >>= 1)
                c += __shfl_down_sync(0xFFFFFFFFu, c, off);
            if (lane == 0 && c) atomicAdd(&slot[it & 31], c);
            __syncthreads();
            if (slot[it & 31] >= KSEL) blo = (unsigned long long)mid;
            else                       bhi = (unsigned long long)mid;
            it++;
            if ((it & 31) == 0) {
                __syncthreads();
                if (tid < 32) slot[tid] = 0;
                __syncthreads();
            }
        }
        const uint32_t T = (uint32_t)blo;

        __syncthreads();
        if (tid < 32) slot[tid] = 0;
        __syncthreads();
        {
            uint32_t ca = 0, ce = 0;
            for (int i = 0; i < VPT; i++) {
                float4 vv = xrow[tid + i * NT];
                const uint32_t k0 = f2key(__float_as_uint(vv.x));
                const uint32_t k1 = f2key(__float_as_uint(vv.y));
                const uint32_t k2 = f2key(__float_as_uint(vv.z));
                const uint32_t k3 = f2key(__float_as_uint(vv.w));
                ca += (k0 > T) + (k1 > T) + (k2 > T) + (k3 > T);
                ce += (k0 == T) + (k1 == T) + (k2 == T) + (k3 == T);
            }
            #pragma unroll
            for (int off = 16; off >= 1; off >>= 1) {
                ca += __shfl_down_sync(0xFFFFFFFFu, ca, off);
                ce += __shfl_down_sync(0xFFFFFFFFu, ce, off);
            }
            if (lane == 0) { atomicAdd(&slot[0], ca); atomicAdd(&slot[1], ce); }
        }
        __syncthreads();
        const uint32_t abv  = slot[0];
        const uint32_t eq   = slot[1];
        const uint32_t remK = KSEL - abv;

        uint32_t tieCut = 0xFFFFFFFFu;
        if (eq != remK) {
            __syncthreads();
            if (tid < 32) slot[tid] = 0;
            __syncthreads();
            int lo = 0, hi = NCOLS - 1, ti = 0;
            while (lo < hi) {
                const int mid = (lo + hi) >> 1;
                uint32_t c = 0;
                for (int i = 0; i < VPT; i++) {
                    float4 vv = xrow[tid + i * NT];
                    const int col0 = (tid + i * NT) * 4;
                    c += (f2key(__float_as_uint(vv.x)) == T && col0 + 0 <= mid);
                    c += (f2key(__float_as_uint(vv.y)) == T && col0 + 1 <= mid);
                    c += (f2key(__float_as_uint(vv.z)) == T && col0 + 2 <= mid);
                    c += (f2key(__float_as_uint(vv.w)) == T && col0 + 3 <= mid);
                }
                #pragma unroll
                for (int off = 16; off >= 1; off >>= 1)
                    c += __shfl_down_sync(0xFFFFFFFFu, c, off);
                if (lane == 0 && c) atomicAdd(&slot[ti & 31], c);
                __syncthreads();
                if (slot[ti & 31] >= remK) hi = mid; else lo = mid + 1;
                ti++;
                if ((ti & 31) == 0) {
                    __syncthreads();
                    if (tid < 32) slot[tid] = 0;
                    __syncthreads();
                }
            }
            tieCut = (uint32_t)lo;
        }

        for (int i = 0; i < VPT; i++) {
            float4 vv = xrow[tid + i * NT];
            const uint32_t col0 = (uint32_t)(tid + i * NT) * 4u;
            const uint32_t k0 = f2key(__float_as_uint(vv.x));
            const uint32_t k1 = f2key(__float_as_uint(vv.y));
            const uint32_t k2 = f2key(__float_as_uint(vv.z));
            const uint32_t k3 = f2key(__float_as_uint(vv.w));
            if (k0 > T || (k0 == T && col0 + 0u <= tieCut)) out[rowOff + col0 + 0] = key2f(k0);
            if (k1 > T || (k1 == T && col0 + 1u <= tieCut)) out[rowOff + col0 + 1] = key2f(k1);
            if (k2 > T || (k2 == T && col0 + 2u <= tieCut)) out[rowOff + col0 + 2] = key2f(k2);
            if (k3 > T || (k3 == T && col0 + 3u <= tieCut)) out[rowOff + col0 + 3] = key2f(k3);
        }
    }
}

extern "C" void kernel_launch(void* const* d_in, const int* in_sizes, int n_in,
                              void* d_out, int out_size)
{
    const float* x = (const float*)d_in[0];
    float* out = (float*)d_out;
    (void)in_sizes; (void)n_in; (void)out_size;

    topk_scatter_kernel<<<NROWS, NT>>>(x, out);
}